// round 5
// baseline (speedup 1.0000x reference)
#include <cuda_runtime.h>
#include <math.h>
#include <stdint.h>

#define TT 1024
#define HH 512
#define CLN 8

// ---------------- packed f32x2 + cluster helpers ----------------
__device__ __forceinline__ unsigned long long pack2(float x, float y) {
    unsigned long long r;
    asm("mov.b64 %0, {%1, %2};" : "=l"(r) : "f"(x), "f"(y));
    return r;
}
__device__ __forceinline__ unsigned long long fma2(unsigned long long a,
                                                   unsigned long long b,
                                                   unsigned long long c) {
    unsigned long long d;
    asm("fma.rn.f32x2 %0, %1, %2, %3;" : "=l"(d) : "l"(a), "l"(b), "l"(c));
    return d;
}
__device__ __forceinline__ unsigned long long add2(unsigned long long a,
                                                   unsigned long long b) {
    unsigned long long d;
    asm("add.rn.f32x2 %0, %1, %2;" : "=l"(d) : "l"(a), "l"(b));
    return d;
}
__device__ __forceinline__ float2 unpack2(unsigned long long v) {
    float2 r;
    asm("mov.b64 {%0, %1}, %2;" : "=f"(r.x), "=f"(r.y) : "l"(v));
    return r;
}
__device__ __forceinline__ uint32_t smem_u32(const void* p) {
    uint32_t a;
    asm("{ .reg .u64 t; cvta.to.shared.u64 t, %1; cvt.u32.u64 %0, t; }"
        : "=r"(a) : "l"(p));
    return a;
}
__device__ __forceinline__ uint32_t ctarank() {
    uint32_t r; asm("mov.u32 %0, %%cluster_ctarank;" : "=r"(r)); return r;
}
__device__ __forceinline__ void st_cluster_f32(uint32_t addr, uint32_t rank, float v) {
    asm volatile("{ .reg .b32 r; mapa.shared::cluster.u32 r, %0, %1; "
                 "st.shared::cluster.f32 [r], %2; }"
                 :: "r"(addr), "r"(rank), "f"(v) : "memory");
}
__device__ __forceinline__ void arrive_cluster(uint32_t addr, uint32_t rank) {
    asm volatile("{ .reg .b32 r; mapa.shared::cluster.u32 r, %0, %1; "
                 "mbarrier.arrive.release.cluster.shared::cluster.b64 _, [r]; }"
                 :: "r"(addr), "r"(rank) : "memory");
}
__device__ __forceinline__ void mbar_init(uint32_t addr, uint32_t cnt) {
    asm volatile("mbarrier.init.shared.b64 [%0], %1;" :: "r"(addr), "r"(cnt) : "memory");
}
__device__ __forceinline__ void mbar_wait(uint32_t addr, uint32_t parity) {
    asm volatile("{\n\t"
                 ".reg .pred P;\n\t"
                 "W%=:\n\t"
                 "mbarrier.try_wait.parity.acquire.cluster.shared::cta.b64 P, [%0], %1, 0x989680;\n\t"
                 "@!P bra W%=;\n\t"
                 "}" :: "r"(addr), "r"(parity) : "memory");
}

// ===================== Phase 1: xw = x @ W[0:512] + b  -> out =====================
// M=65536, N=512, K=512. BM=128, BN=64, BK=16, 256 threads, 8x4 per thread.
// A tile stored DUPLICATED ({a,a} float2) so fma2 eats LDS.64 directly, no packs.
__global__ void __launch_bounds__(256) gemm_xw_kernel(
    const float* __restrict__ x, const float* __restrict__ Wg,
    const float* __restrict__ bias, float* __restrict__ C)
{
    __shared__ __align__(16) float2 As2[16][132];  // [BK][BM+4] duplicated
    __shared__ __align__(16) float  Bs[16][68];    // [BK][BN+4]

    const int tid = threadIdx.x;
    const int tn  = tid & 15;
    const int tm  = tid >> 4;
    const int m0  = blockIdx.x * 128;
    const int n0  = blockIdx.y * 64;

    unsigned long long acc[8][2];
#pragma unroll
    for (int i = 0; i < 8; i++) { acc[i][0] = 0ull; acc[i][1] = 0ull; }

    for (int k0 = 0; k0 < 512; k0 += 16) {
#pragma unroll
        for (int i = tid; i < 512; i += 256) {
            int m = i >> 2, kq = i & 3;
            float4 v = *(const float4*)(x + (size_t)(m0 + m) * 512 + k0 + kq * 4);
            As2[kq * 4 + 0][m] = make_float2(v.x, v.x);
            As2[kq * 4 + 1][m] = make_float2(v.y, v.y);
            As2[kq * 4 + 2][m] = make_float2(v.z, v.z);
            As2[kq * 4 + 3][m] = make_float2(v.w, v.w);
        }
        {
            int kk = tid >> 4, nq = tid & 15;
            float4 v = *(const float4*)(Wg + (size_t)(k0 + kk) * 512 + n0 + nq * 4);
            *(float4*)&Bs[kk][nq * 4] = v;
        }
        __syncthreads();
#pragma unroll
        for (int kk = 0; kk < 16; kk++) {
            ulonglong2 bb = *(const ulonglong2*)&Bs[kk][tn * 4];
#pragma unroll
            for (int i = 0; i < 8; i++) {
                unsigned long long ad = *(const unsigned long long*)&As2[kk][tm * 8 + i];
                acc[i][0] = fma2(ad, bb.x, acc[i][0]);
                acc[i][1] = fma2(ad, bb.y, acc[i][1]);
            }
        }
        __syncthreads();
    }

    float b0 = bias[n0 + tn * 4 + 0];
    float b1 = bias[n0 + tn * 4 + 1];
    float b2 = bias[n0 + tn * 4 + 2];
    float b3 = bias[n0 + tn * 4 + 3];
#pragma unroll
    for (int i = 0; i < 8; i++) {
        int m = m0 + tm * 8 + i;
        float2 p0 = unpack2(acc[i][0]);
        float2 p1 = unpack2(acc[i][1]);
        float4 o;
        o.x = p0.x + b0; o.y = p0.y + b1; o.z = p1.x + b2; o.w = p1.y + b3;
        *(float4*)(C + (size_t)m * 512 + n0 + tn * 4) = o;
    }
}

// ===================== Phase 2: recurrence via 8-CTA clusters ======================
// 16 clusters x 8 CTAs. Cluster g: batches 4g..4g+3. CTA rank c: output cols 64c..64c+63.
// Wh slice in registers as k-pairs {w_k, w_{k+1}}; h plain in SMEM (LDS.128 broadcast
// gives {h_k,h_{k+1}} u64 pairs directly -> zero packing in the hot loop).
// h exchange: direct DSMEM pushes to all 8 peers + mbarrier arrive/wait (no L2, no spin).
__global__ void __launch_bounds__(256, 1) __cluster_dims__(CLN, 1, 1)
recurrent_kernel(const float* __restrict__ Wg, float* __restrict__ out)
{
    __shared__ __align__(16) float hbuf[2][4][512];   // [parity][batch][k]
    __shared__ __align__(16) float red[8][268];       // per-K-chunk partials
    __shared__ __align__(8)  unsigned long long mb[2];

    const int tid = threadIdx.x;
    const int g   = blockIdx.x >> 3;       // cluster id 0..15
    const uint32_t c = ctarank();          // 0..7 (== blockIdx.x & 7)
    const int kc  = tid >> 5;              // K-chunk 0..7 (warp id)
    const int jg  = tid & 31;              // cols 2jg, 2jg+1 within slice
    const int bo  = tid >> 6;              // epilogue batch 0..3
    const int col = tid & 63;              // epilogue column within slice

    const uint32_t hb_off = smem_u32(hbuf);
    const uint32_t mb_off = smem_u32(mb);

    if (tid == 0) { mbar_init(mb_off, CLN); mbar_init(mb_off + 8, CLN); }
    // zero both h parity buffers (h_{-1} = 0)
    for (int i = tid; i < 2 * 4 * 512 / 4; i += 256)
        ((float4*)hbuf)[i] = make_float4(0.f, 0.f, 0.f, 0.f);
    __syncthreads();
    // all mbarriers/buffers initialized cluster-wide before anyone can push/arrive
    asm volatile("barrier.cluster.arrive.aligned;" ::: "memory");
    asm volatile("barrier.cluster.wait.aligned;" ::: "memory");

    // ---- Wh slice into registers as k-pairs: w[(k2<<1)|cc] = {Wh[2k2][cc], Wh[2k2+1][cc]} ----
    unsigned long long w[64];
    {
        const float* wbase = Wg + (size_t)(512 + kc * 64) * 512 + c * 64 + jg * 2;
#pragma unroll
        for (int k2 = 0; k2 < 32; k2++) {
#pragma unroll
            for (int cc = 0; cc < 2; cc++) {
                float lo = wbase[(size_t)(2 * k2) * 512 + cc];
                float hi = wbase[(size_t)(2 * k2 + 1) * 512 + cc];
                w[(k2 << 1) | cc] = pack2(lo, hi);
            }
        }
    }

    float* outrow = out + (size_t)(g * 4 + bo) * TT * HH + c * 64 + col;
    // my output slot byte-offset inside any CTA's hbuf (per parity)
    const uint32_t slot0 = hb_off + (uint32_t)((0 * 4 + bo) * 512 + c * 64 + col) * 4;
    const uint32_t slot1 = hb_off + (uint32_t)((1 * 4 + bo) * 512 + c * 64 + col) * 4;

    for (int t = 0; t < TT; t++) {
        float xwv = outrow[(size_t)t * HH];     // phase-1 result, overlaps compute

        const int p = t & 1;
        // 8 accumulators: [batch][colpair], each holds {sum over even k, sum over odd k}
        unsigned long long a00 = 0, a01 = 0, a10 = 0, a11 = 0;
        unsigned long long a20 = 0, a21 = 0, a30 = 0, a31 = 0;
        const ulonglong2* h0 = (const ulonglong2*)&hbuf[p][0][kc * 64];
        const ulonglong2* h1 = (const ulonglong2*)&hbuf[p][1][kc * 64];
        const ulonglong2* h2 = (const ulonglong2*)&hbuf[p][2][kc * 64];
        const ulonglong2* h3 = (const ulonglong2*)&hbuf[p][3][kc * 64];
#pragma unroll
        for (int i4 = 0; i4 < 16; i4++) {       // 4 k's per iteration
            ulonglong2 hb0 = h0[i4];            // {h_k,h_k+1},{h_k+2,h_k+3} (broadcast)
            ulonglong2 hb1 = h1[i4];
            ulonglong2 hb2 = h2[i4];
            ulonglong2 hb3 = h3[i4];
            unsigned long long wl0 = w[(2 * i4) << 1], wl1 = w[((2 * i4) << 1) | 1];
            unsigned long long wh0 = w[(2 * i4 + 1) << 1], wh1 = w[((2 * i4 + 1) << 1) | 1];
            a00 = fma2(hb0.x, wl0, a00); a01 = fma2(hb0.x, wl1, a01);
            a00 = fma2(hb0.y, wh0, a00); a01 = fma2(hb0.y, wh1, a01);
            a10 = fma2(hb1.x, wl0, a10); a11 = fma2(hb1.x, wl1, a11);
            a10 = fma2(hb1.y, wh0, a10); a11 = fma2(hb1.y, wh1, a11);
            a20 = fma2(hb2.x, wl0, a20); a21 = fma2(hb2.x, wl1, a21);
            a20 = fma2(hb2.y, wh0, a20); a21 = fma2(hb2.y, wh1, a21);
            a30 = fma2(hb3.x, wl0, a30); a31 = fma2(hb3.x, wl1, a31);
            a30 = fma2(hb3.y, wh0, a30); a31 = fma2(hb3.y, wh1, a31);
        }
        // horizontal even+odd, stash per-chunk partials as float2 {col 2jg, col 2jg+1}
        {
            float2 e0 = unpack2(a00), o0 = unpack2(a01);
            float2 e1 = unpack2(a10), o1 = unpack2(a11);
            float2 e2 = unpack2(a20), o2 = unpack2(a21);
            float2 e3 = unpack2(a30), o3 = unpack2(a31);
            *(float2*)&red[kc][0 * 64 + jg * 2] = make_float2(e0.x + e0.y, o0.x + o0.y);
            *(float2*)&red[kc][1 * 64 + jg * 2] = make_float2(e1.x + e1.y, o1.x + o1.y);
            *(float2*)&red[kc][2 * 64 + jg * 2] = make_float2(e2.x + e2.y, o2.x + o2.y);
            *(float2*)&red[kc][3 * 64 + jg * 2] = make_float2(e3.x + e3.y, o3.x + o3.y);
        }
        __syncthreads();

        // epilogue: one (batch, col) output per thread
        float z = xwv;
#pragma unroll
        for (int k2 = 0; k2 < 8; k2++) z += red[k2][bo * 64 + col];
        float hv = tanhf(z);
        outrow[(size_t)t * HH] = hv;            // this IS the output

        if (t + 1 < TT) {
            // push h_t into every cluster CTA's hbuf[(t+1)&1] (including self)
            const uint32_t slot = (p == 0) ? slot1 : slot0;  // parity (t+1)&1
#pragma unroll
            for (uint32_t r = 0; r < CLN; r++) st_cluster_f32(slot, r, hv);
            __syncthreads();                    // all pushes issued before arrive
            const uint32_t mbq = mb_off + (uint32_t)(((t + 1) & 1) << 3);
            if (tid < CLN) arrive_cluster(mbq, (uint32_t)tid);
            mbar_wait(mbq, (t >> 1) & 1);
        }
    }
}

// ======================================================================================
extern "C" void kernel_launch(void* const* d_in, const int* in_sizes, int n_in,
                              void* d_out, int out_size) {
    (void)in_sizes; (void)n_in; (void)out_size;
    const float* x  = (const float*)d_in[0];   // [64,1024,512]
    const float* Wg = (const float*)d_in[1];   // [1024,512]
    const float* bb = (const float*)d_in[2];   // [512]
    float* out = (float*)d_out;                // [64,1024,512]

    gemm_xw_kernel<<<dim3(512, 8), 256>>>(x, Wg, bb, out);
    recurrent_kernel<<<128, 256>>>(Wg, out);
}